// round 8
// baseline (speedup 1.0000x reference)
#include <cuda_runtime.h>
#include <cstdint>
#include <math.h>

// ---------------- fast-math row loss (tolerance 1e-3, margin ~5e-8) --------
__device__ __forceinline__ float row_loss(const float* __restrict__ p,
                                          const float* __restrict__ t) {
    float dx = p[0] - t[0];
    float dy = p[1] - t[1];

    float wp = fminf(fmaxf(p[2], 1e-7f), 1e7f);
    float hp = fminf(fmaxf(p[3], 1e-7f), 1e7f);
    float ap = 0.25f * wp * wp;
    float bp = 0.25f * hp * hp;
    float sp, cp;
    __sincosf(p[4], &sp, &cp);           // |r| < pi/2: MUFU path accurate
    float cp2 = cp * cp, sp2 = sp * sp;
    float p00 = ap * cp2 + bp * sp2;
    float p11 = ap * sp2 + bp * cp2;
    float p01 = (ap - bp) * sp * cp;

    float wt = fminf(fmaxf(t[2], 1e-7f), 1e7f);
    float ht = fminf(fmaxf(t[3], 1e-7f), 1e7f);
    float at = 0.25f * wt * wt;
    float bt = 0.25f * ht * ht;
    float st, ct;
    __sincosf(t[4], &st, &ct);
    float ct2 = ct * ct, st2 = st * st;
    float t00 = at * ct2 + bt * st2;
    float t11 = at * st2 + bt * ct2;
    float t01 = (at - bt) * st * ct;

    float det_p = p00 * p11 - p01 * p01;
    float det_t = t00 * t11 - t01 * t01;
    float inv_det_t = __fdividef(1.0f, det_t);

    float term1 = (dx * dx * t11 - 2.0f * dx * dy * t01 + dy * dy * t00) * inv_det_t;
    float tr = (t11 * p00 + t00 * p11 - 2.0f * t01 * p01) * inv_det_t;

    float dis = term1 + tr + __logf(__fdividef(det_t, det_p)) - 2.0f;
    float kl = fmaxf(dis, 1e-6f);
    float L = __logf(1.0f + kl);
    return __fdividef(L, 1.0f + L);      // 1 - 1/(1+L), tau = 1
}

// ---------------- cp.async smem ring pipeline -------------------------------
// Each stage = 256 rows = 320 float4 per input stream (5 KB x 2).
// Loads are lane-consecutive cp.async.cg (coalesced: 4 lines / warp-instr,
// L1-bypass -> no L1tex replay amplification), 4 stages in flight.
#define STAGES 4
#define TILE_ROWS 256
#define TILE_V4   (TILE_ROWS * 5 / 4)        // 320 float4 per stream
#define CTAS_PER_SM 5

__device__ __forceinline__ void cp_async16(void* smem_dst, const void* gsrc) {
    uint32_t s = (uint32_t)__cvta_generic_to_shared(smem_dst);
    asm volatile("cp.async.cg.shared.global [%0], [%1], 16;"
                 :: "r"(s), "l"(gsrc) : "memory");
}
__device__ __forceinline__ void cp_commit() {
    asm volatile("cp.async.commit_group;" ::: "memory");
}
__device__ __forceinline__ void cp_wait3() {
    asm volatile("cp.async.wait_group 3;" ::: "memory");
}

__global__ void __launch_bounds__(256, CTAS_PER_SM)
kld_cpasync_kernel(const float4* __restrict__ pred,
                   const float4* __restrict__ targ,
                   float* __restrict__ out, int ntiles) {
    __shared__ alignas(128) float4 sp[STAGES][TILE_V4];
    __shared__ alignas(128) float4 st[STAGES][TILE_V4];

    const int tid = threadIdx.x;

    // issue one stage's loads (coalesced, 640 float4 across 256 threads)
    auto issue_stage = [&](int s, long long tile) {
        if (tile < ntiles) {
            size_t vbase = (size_t)tile * TILE_V4;
            for (int k = tid; k < 2 * TILE_V4; k += 256) {
                if (k < TILE_V4)
                    cp_async16(&sp[s][k], &pred[vbase + k]);
                else
                    cp_async16(&st[s][k - TILE_V4], &targ[vbase + k - TILE_V4]);
            }
        }
        cp_commit();                     // commit even if empty (group order)
    };

    // prologue: fill the ring
#pragma unroll
    for (int s = 0; s < STAGES; s++)
        issue_stage(s, (long long)blockIdx.x + (long long)s * gridDim.x);

    int j = 0;
    for (long long tile = blockIdx.x; tile < ntiles; tile += gridDim.x, j++) {
        int s = j & (STAGES - 1);
        cp_wait3();                      // oldest group (stage s) complete
        __syncthreads();                 // its smem visible to all lanes

        const float* pf = reinterpret_cast<const float*>(&sp[s][0]);
        const float* tf = reinterpret_cast<const float*>(&st[s][0]);
        float r = row_loss(pf + 5 * tid, tf + 5 * tid);  // stride-5: no conflicts
        __stcs(&out[tile * TILE_ROWS + tid], r);

        __syncthreads();                 // all lanes done reading stage s
        issue_stage(s, tile + (long long)STAGES * gridDim.x);
    }
}

// Scalar tail for rows not covered by full 256-row tiles (not hit for N=4M).
__global__ void kld_loss_tail_kernel(const float* __restrict__ pred,
                                     const float* __restrict__ targ,
                                     float* __restrict__ out,
                                     int start, int n) {
    int i = start + blockIdx.x * blockDim.x + threadIdx.x;
    if (i >= n) return;
    out[i] = row_loss(pred + 5 * i, targ + 5 * i);
}

extern "C" void kernel_launch(void* const* d_in, const int* in_sizes, int n_in,
                              void* d_out, int out_size) {
    const float* pred = (const float*)d_in[0];
    const float* targ = (const float*)d_in[1];
    float* out = (float*)d_out;

    int n = in_sizes[0] / 5;       // rows
    int ntiles = n / TILE_ROWS;    // 15625 for N=4M
    int rem_start = ntiles * TILE_ROWS;

    if (ntiles > 0) {
        int grid = 152 * CTAS_PER_SM;   // persistent
        if (grid > ntiles) grid = ntiles;
        kld_cpasync_kernel<<<grid, 256>>>(
            (const float4*)pred, (const float4*)targ, out, ntiles);
    }
    if (rem_start < n) {
        int rem = n - rem_start;
        kld_loss_tail_kernel<<<(rem + 127) / 128, 128>>>(pred, targ, out,
                                                         rem_start, n);
    }
}